// round 2
// baseline (speedup 1.0000x reference)
#include <cuda_runtime.h>

#define STRIDE 68
#define NTHREADS 256
// 4 big buffers [64][68] + s_d(64) + s_mean(64) + s_sh(128) + s_out(64) + s_obs(896)
#define SMEM_FLOATS (4*64*STRIDE + 64 + 64 + 128 + 64 + 896)

// Computes 4x4 tile of C = A(64x64) @ B(64x64), A,B in shared with row stride STRIDE.
__device__ __forceinline__ void mm64_tile(const float* __restrict__ A,
                                          const float* __restrict__ B,
                                          float acc[4][4], int i0, int j0)
{
#pragma unroll
    for (int r = 0; r < 4; r++)
#pragma unroll
        for (int c = 0; c < 4; c++) acc[r][c] = 0.0f;

#pragma unroll 4
    for (int k = 0; k < 64; k += 4) {
        float4 b0 = *(const float4*)&B[(k + 0) * STRIDE + j0];
        float4 b1 = *(const float4*)&B[(k + 1) * STRIDE + j0];
        float4 b2 = *(const float4*)&B[(k + 2) * STRIDE + j0];
        float4 b3 = *(const float4*)&B[(k + 3) * STRIDE + j0];
#pragma unroll
        for (int r = 0; r < 4; r++) {
            float4 a = *(const float4*)&A[(i0 + r) * STRIDE + k];
            acc[r][0] = fmaf(a.x, b0.x, acc[r][0]);
            acc[r][0] = fmaf(a.y, b1.x, acc[r][0]);
            acc[r][0] = fmaf(a.z, b2.x, acc[r][0]);
            acc[r][0] = fmaf(a.w, b3.x, acc[r][0]);

            acc[r][1] = fmaf(a.x, b0.y, acc[r][1]);
            acc[r][1] = fmaf(a.y, b1.y, acc[r][1]);
            acc[r][1] = fmaf(a.z, b2.y, acc[r][1]);
            acc[r][1] = fmaf(a.w, b3.y, acc[r][1]);

            acc[r][2] = fmaf(a.x, b0.z, acc[r][2]);
            acc[r][2] = fmaf(a.y, b1.z, acc[r][2]);
            acc[r][2] = fmaf(a.z, b2.z, acc[r][2]);
            acc[r][2] = fmaf(a.w, b3.z, acc[r][2]);

            acc[r][3] = fmaf(a.x, b0.w, acc[r][3]);
            acc[r][3] = fmaf(a.y, b1.w, acc[r][3]);
            acc[r][3] = fmaf(a.z, b2.w, acc[r][3]);
            acc[r][3] = fmaf(a.w, b3.w, acc[r][3]);
        }
    }
}

__global__ __launch_bounds__(NTHREADS) void pgcn_kernel(
    const float* __restrict__ device_obs,   // [B,63,14]
    const float* __restrict__ server_obs,   // [B,3]
    const float* __restrict__ adjacency,    // [B,64,64]
    const float* __restrict__ W_dev,        // [14,64]
    const float* __restrict__ b_dev,        // [64]
    const float* __restrict__ W_srv,        // [3,64]
    const float* __restrict__ b_srv,        // [64]
    const float* __restrict__ W1, const float* __restrict__ b1,  // [64,64],[64]
    const float* __restrict__ W2, const float* __restrict__ b2,
    const float* __restrict__ W3, const float* __restrict__ b3,
    const float* __restrict__ Wf1,          // [192,128]
    const float* __restrict__ bf1,          // [128]
    const float* __restrict__ Wf2,          // [128,1]
    const float* __restrict__ bf2,          // [1]
    float* __restrict__ out)                // [B,63]
{
    extern __shared__ float sm[];
    float* s_adj  = sm;                       // [64][STRIDE] normalized adjacency
    float* s_h    = s_adj  + 64 * STRIDE;     // [64][STRIDE] node features
    float* s_t    = s_h    + 64 * STRIDE;     // [64][STRIDE] temp (adj @ h)
    float* s_w    = s_t    + 64 * STRIDE;     // [64][STRIDE] staged weights
    float* s_d    = s_w    + 64 * STRIDE;     // [64] d^{-1/2}
    float* s_mean = s_d    + 64;              // [64]
    float* s_sh   = s_mean + 64;              // [128] shared head vector
    float* s_out  = s_sh   + 128;             // [64]
    float* s_obs  = s_out  + 64;              // [896] device_obs (63*14)

    const int b   = blockIdx.x;
    const int tid = threadIdx.x;
    const int tc  = tid & 15;        // column group 0..15
    const int tr  = tid >> 4;        // row group 0..15
    const int i0  = tr << 2;
    const int j0  = tc << 2;

    // ---- Load adjacency + observations ----
    const float* adjg = adjacency + (size_t)b * 4096;
#pragma unroll
    for (int idx = tid; idx < 1024; idx += NTHREADS) {
        int i = idx >> 4;
        int j4 = (idx & 15) << 2;
        float4 v = ((const float4*)adjg)[idx];
        *(float4*)&s_adj[i * STRIDE + j4] = v;
    }
    const float* dob = device_obs + (size_t)b * 882;  // 63*14
    for (int idx = tid; idx < 882; idx += NTHREADS) s_obs[idx] = dob[idx];
    const float so0 = server_obs[b * 3 + 0];
    const float so1 = server_obs[b * 3 + 1];
    const float so2 = server_obs[b * 3 + 2];
    __syncthreads();

    // ---- degree -> d^{-1/2} ----
    if (tid < 64) {
        float deg = 0.0f;
#pragma unroll 8
        for (int j = 0; j < 64; j++) deg += s_adj[tid * STRIDE + j];
        s_d[tid] = rsqrtf(fmaxf(deg, 1.0f));
    }
    __syncthreads();

    // ---- normalize adjacency in place ----
    for (int idx = tid; idx < 4096; idx += NTHREADS) {
        int i = idx >> 6, j = idx & 63;
        s_adj[i * STRIDE + j] *= s_d[i] * s_d[j];
    }

    // ---- build x: device rows 0..62 ----
    for (int idx = tid; idx < 63 * 64; idx += NTHREADS) {
        int i = idx >> 6, j = idx & 63;
        float acc = b_dev[j];
        const float* o = s_obs + i * 14;
#pragma unroll
        for (int k = 0; k < 14; k++) acc = fmaf(o[k], W_dev[k * 64 + j], acc);
        s_h[i * STRIDE + j] = fmaxf(acc, 0.0f);
    }
    // ---- server row 63 ----
    if (tid < 64) {
        float acc = b_srv[tid];
        acc = fmaf(so0, W_srv[tid], acc);
        acc = fmaf(so1, W_srv[64 + tid], acc);
        acc = fmaf(so2, W_srv[128 + tid], acc);
        s_h[63 * STRIDE + tid] = fmaxf(acc, 0.0f);
    }
    __syncthreads();

    // ---- 3 GCN layers: h = relu((adj_norm @ h) @ W + b) ----
    const float* Ws[3] = {W1, W2, W3};
    const float* bs[3] = {b1, b2, b3};
#pragma unroll 1
    for (int L = 0; L < 3; L++) {
        // stage W into shared
        const float* Wg = Ws[L];
        for (int idx = tid; idx < 1024; idx += NTHREADS) {
            int i = idx >> 4;
            int j4 = (idx & 15) << 2;
            *(float4*)&s_w[i * STRIDE + j4] = ((const float4*)Wg)[idx];
        }
        __syncthreads();

        // t = adj_norm @ h
        {
            float acc[4][4];
            mm64_tile(s_adj, s_h, acc, i0, j0);
#pragma unroll
            for (int r = 0; r < 4; r++) {
                float4 v = make_float4(acc[r][0], acc[r][1], acc[r][2], acc[r][3]);
                *(float4*)&s_t[(i0 + r) * STRIDE + j0] = v;
            }
        }
        __syncthreads();

        // h = relu(t @ W + b)
        {
            float acc[4][4];
            mm64_tile(s_t, s_w, acc, i0, j0);
            float4 bb = *(const float4*)&bs[L][j0];
#pragma unroll
            for (int r = 0; r < 4; r++) {
                float4 v;
                v.x = fmaxf(acc[r][0] + bb.x, 0.0f);
                v.y = fmaxf(acc[r][1] + bb.y, 0.0f);
                v.z = fmaxf(acc[r][2] + bb.z, 0.0f);
                v.w = fmaxf(acc[r][3] + bb.w, 0.0f);
                *(float4*)&s_h[(i0 + r) * STRIDE + j0] = v;
            }
        }
        __syncthreads();
    }

    // ---- head: dev_mean + s_out init ----
    if (tid < 64) {
        float m = 0.0f;
#pragma unroll 8
        for (int i = 0; i < 63; i++) m += s_h[i * STRIDE + tid];
        s_mean[tid] = m * (1.0f / 63.0f);
        s_out[tid] = bf2[0];
    }
    __syncthreads();

    // shared head vector: bf1 + dev_mean @ Wf1[64:128] + server_hidden @ Wf1[128:192]
    // concurrently: other half stages Wf1[0:64, 0:64] into s_w
    if (tid < 128) {
        float acc = bf1[tid];
        const float* srv = &s_h[63 * STRIDE];
#pragma unroll 4
        for (int k = 0; k < 64; k++) {
            acc = fmaf(s_mean[k], Wf1[(64 + k) * 128 + tid], acc);
            acc = fmaf(srv[k],   Wf1[(128 + k) * 128 + tid], acc);
        }
        s_sh[tid] = acc;
    } else {
        for (int idx = tid - 128; idx < 1024; idx += 128) {
            int kk = idx >> 4;
            int j4 = (idx & 15) << 2;
            *(float4*)&s_w[kk * STRIDE + j4] = *(const float4*)&Wf1[kk * 128 + j4];
        }
    }
    __syncthreads();

    // ---- head GEMM in two 64-col chunks: u = relu(h @ Wf1_chunk + s_sh), out += u @ Wf2_chunk
#pragma unroll 1
    for (int c = 0; c < 2; c++) {
        float acc[4][4];
        mm64_tile(s_h, s_w, acc, i0, j0);

        float4 sv = *(const float4*)&s_sh[c * 64 + j0];
        float4 w2 = *(const float4*)&Wf2[c * 64 + j0];
        float part[4];
#pragma unroll
        for (int r = 0; r < 4; r++) {
            float u0 = fmaxf(acc[r][0] + sv.x, 0.0f);
            float u1 = fmaxf(acc[r][1] + sv.y, 0.0f);
            float u2 = fmaxf(acc[r][2] + sv.z, 0.0f);
            float u3 = fmaxf(acc[r][3] + sv.w, 0.0f);
            part[r] = u0 * w2.x + u1 * w2.y + u2 * w2.z + u3 * w2.w;
        }
        // reduce over the 16 column-group threads (contiguous 16-lane segments)
#pragma unroll
        for (int off = 8; off > 0; off >>= 1) {
#pragma unroll
            for (int r = 0; r < 4; r++)
                part[r] += __shfl_down_sync(0xffffffffu, part[r], off, 16);
        }
        if (tc == 0) {
#pragma unroll
            for (int r = 0; r < 4; r++) atomicAdd(&s_out[i0 + r], part[r]);
        }
        __syncthreads();
        if (c == 0) {
            // stage Wf1[0:64, 64:128]
            for (int idx = tid; idx < 1024; idx += NTHREADS) {
                int kk = idx >> 4;
                int j4 = (idx & 15) << 2;
                *(float4*)&s_w[kk * STRIDE + j4] = *(const float4*)&Wf1[kk * 128 + 64 + j4];
            }
            __syncthreads();
        }
    }

    // ---- write output (63 devices) ----
    for (int i = tid; i < 63; i += NTHREADS)
        out[(size_t)b * 63 + i] = s_out[i];
}

extern "C" void kernel_launch(void* const* d_in, const int* in_sizes, int n_in,
                              void* d_out, int out_size)
{
    const float* device_obs = (const float*)d_in[0];
    const float* server_obs = (const float*)d_in[1];
    const float* adjacency  = (const float*)d_in[2];
    const float* W_dev = (const float*)d_in[3];
    const float* b_dev = (const float*)d_in[4];
    const float* W_srv = (const float*)d_in[5];
    const float* b_srv = (const float*)d_in[6];
    const float* W1 = (const float*)d_in[7];
    const float* b1 = (const float*)d_in[8];
    const float* W2 = (const float*)d_in[9];
    const float* b2 = (const float*)d_in[10];
    const float* W3 = (const float*)d_in[11];
    const float* b3 = (const float*)d_in[12];
    const float* Wf1 = (const float*)d_in[13];
    const float* bf1 = (const float*)d_in[14];
    const float* Wf2 = (const float*)d_in[15];
    const float* bf2 = (const float*)d_in[16];

    const int B = in_sizes[0] / (63 * 14);
    const size_t smem = SMEM_FLOATS * sizeof(float);
    cudaFuncSetAttribute(pgcn_kernel, cudaFuncAttributeMaxDynamicSharedMemorySize, (int)smem);
    pgcn_kernel<<<B, NTHREADS, smem>>>(
        device_obs, server_obs, adjacency,
        W_dev, b_dev, W_srv, b_srv,
        W1, b1, W2, b2, W3, b3,
        Wf1, bf1, Wf2, bf2,
        (float*)d_out);
}